// round 5
// baseline (speedup 1.0000x reference)
#include <cuda_runtime.h>
#include <math.h>

#define BB 256
#define NN 2048
#define NSUM 22   // M(6 sym), C(9), mw(3), yw(3), wsum(1)
#define SPLIT 8   // N-splits per batch in stage 1

// scratch (no allocations allowed)
__device__ float g_part[BB * SPLIT * NSUM];
__device__ float g_sums[BB * NSUM];
__device__ float g_inv_scale;

// ---------------------------------------------------------------------------
// Stage 1: partial weighted sums. grid = BB*SPLIT = 2048 blocks, 128 threads.
// Each thread processes one float2 (2 points): 7 LDG.64 per thread.
// 262k threads total -> ~86% occupancy, maximizes DRAM latency hiding.
// sums layout: [0..5]=M(00,01,02,11,12,22), [6..14]=C[i][j] (i=m idx, j=y idx),
//              [15..17]=mw, [18..20]=yw, [21]=wsum
// ---------------------------------------------------------------------------
__global__ __launch_bounds__(128) void reduce_kernel(
    const float* __restrict__ src, const float* __restrict__ trg,
    const float* __restrict__ w)
{
    int bx = blockIdx.x;
    int b = bx >> 3;
    int split = bx & 7;
    const int NV2 = NN / 2;            // 1024 float2 per row
    int n = split * 128 + threadIdx.x; // 0..1023

    const float2* m0 = (const float2*)(src + (size_t)b * 4 * NN);
    const float2* m1 = m0 + NV2;
    const float2* m2 = m0 + 2 * NV2;
    const float2* y0 = (const float2*)(trg + (size_t)b * 4 * NN);
    const float2* y1 = y0 + NV2;
    const float2* y2 = y0 + 2 * NV2;
    const float2* wp = (const float2*)(w + (size_t)b * NN);

    float2 wv2 = __ldg(wp + n);
    float2 a02 = __ldg(m0 + n), a12 = __ldg(m1 + n), a22 = __ldg(m2 + n);
    float2 c02 = __ldg(y0 + n), c12 = __ldg(y1 + n), c22 = __ldg(y2 + n);

    float acc[NSUM];
#pragma unroll
    for (int k = 0; k < NSUM; k++) acc[k] = 0.f;

    const float* wvp = &wv2.x;
    const float* a0p = &a02.x; const float* a1p = &a12.x; const float* a2p = &a22.x;
    const float* c0p = &c02.x; const float* c1p = &c12.x; const float* c2p = &c22.x;
#pragma unroll
    for (int l = 0; l < 2; l++) {
        float wv = wvp[l];
        float a0 = a0p[l], a1 = a1p[l], a2 = a2p[l];
        float c0 = c0p[l], c1 = c1p[l], c2 = c2p[l];
        float w0 = wv * a0, w1 = wv * a1, w2 = wv * a2;
        acc[0]  += w0 * a0; acc[1]  += w0 * a1; acc[2]  += w0 * a2;
        acc[3]  += w1 * a1; acc[4]  += w1 * a2; acc[5]  += w2 * a2;
        acc[6]  += w0 * c0; acc[7]  += w0 * c1; acc[8]  += w0 * c2;
        acc[9]  += w1 * c0; acc[10] += w1 * c1; acc[11] += w1 * c2;
        acc[12] += w2 * c0; acc[13] += w2 * c1; acc[14] += w2 * c2;
        acc[15] += w0;      acc[16] += w1;      acc[17] += w2;
        acc[18] += wv * c0; acc[19] += wv * c1; acc[20] += wv * c2;
        acc[21] += wv;
    }

    // warp reduce all 22
#pragma unroll
    for (int k = 0; k < NSUM; k++)
#pragma unroll
        for (int off = 16; off > 0; off >>= 1)
            acc[k] += __shfl_xor_sync(0xFFFFFFFFu, acc[k], off);

    __shared__ float sm[4][NSUM];
    int wid = threadIdx.x >> 5, lane = threadIdx.x & 31;
    if (lane == 0)
#pragma unroll
        for (int k = 0; k < NSUM; k++) sm[wid][k] = acc[k];
    __syncthreads();
    if (threadIdx.x < NSUM) {
        float s = sm[0][threadIdx.x] + sm[1][threadIdx.x]
                + sm[2][threadIdx.x] + sm[3][threadIdx.x];
        g_part[(bx) * NSUM + threadIdx.x] = s;
    }
}

// ---------------------------------------------------------------------------
// Stage 2: combine partials + robust fp32 pose solve + global Frobenius norm.
// One thread per batch.
// ---------------------------------------------------------------------------
__global__ __launch_bounds__(256) void pose_kernel(
    const float* __restrict__ tsv_in, float* __restrict__ tout)
{
    int b = threadIdx.x;

    // combine SPLIT partials
    float s[NSUM];
#pragma unroll
    for (int k = 0; k < NSUM; k++) s[k] = 0.f;
#pragma unroll
    for (int p = 0; p < SPLIT; p++) {
        const float* gp = g_part + (b * SPLIT + p) * NSUM;
#pragma unroll
        for (int k = 0; k < NSUM; k++) s[k] += __ldg(gp + k);
    }
#pragma unroll
    for (int k = 0; k < NSUM; k++) g_sums[b * NSUM + k] = s[k];

    // ---- per-batch Q norm^2 (closed form) ----
    float nq = 3.f * (s[0]*s[0] + s[3]*s[3] + s[5]*s[5])
             + 6.f * (s[1]*s[1] + s[2]*s[2] + s[4]*s[4]);
#pragma unroll
    for (int k = 6; k < 15; k++) nq += 2.f * s[k] * s[k];
#pragma unroll
    for (int k = 15; k < 18; k++) nq += 6.f * s[k] * s[k];
#pragma unroll
    for (int k = 18; k < 21; k++) nq += 2.f * s[k] * s[k];
    nq += 3.f * s[21] * s[21];

#pragma unroll
    for (int off = 16; off > 0; off >>= 1)
        nq += __shfl_xor_sync(0xFFFFFFFFu, nq, off);
    __shared__ float smq[8];
    int wid = threadIdx.x >> 5, lane = threadIdx.x & 31;
    if (lane == 0) smq[wid] = nq;
    __syncthreads();
    if (threadIdx.x == 0) {
        float tot = 0.f;
#pragma unroll
        for (int ww = 0; ww < 8; ww++) tot += smq[ww];
        float x = rsqrtf(tot);
        x = x * (1.5f - 0.5f * tot * x * x);  // Newton refine
        g_inv_scale = x;
    }

    // ---- pose (fp32, robust: never divide by smallest singular value) ----
    float inv_ws = 1.f / s[21];
    float mw[3] = {s[15], s[16], s[17]};
    float yw[3] = {s[18], s[19], s[20]};

    // H = C^T - yw mw^T / ws   (C[i][j] = s[6+3i+j], i indexes m, j indexes y)
    float H[3][3];
#pragma unroll
    for (int i = 0; i < 3; i++)
#pragma unroll
        for (int j = 0; j < 3; j++)
            H[i][j] = s[6 + 3 * j + i] - yw[i] * mw[j] * inv_ws;

    float mum[3], muy[3];
#pragma unroll
    for (int i = 0; i < 3; i++) { mum[i] = mw[i] * inv_ws; muy[i] = yw[i] * inv_ws; }

    // A = H^T H (symmetric)
    float A[3][3];
#pragma unroll
    for (int i = 0; i < 3; i++)
#pragma unroll
        for (int j = 0; j < 3; j++) {
            float t = 0.f;
#pragma unroll
            for (int k = 0; k < 3; k++) t += H[k][i] * H[k][j];
            A[i][j] = t;
        }

    // Jacobi eigendecomposition: A = V L V^T
    float V[3][3] = {{1,0,0},{0,1,0},{0,0,1}};
    for (int sweep = 0; sweep < 6; sweep++) {
#pragma unroll
        for (int r = 0; r < 3; r++) {
            int p = (r == 2) ? 1 : 0;
            int q = (r == 0) ? 1 : 2;
            float apq = A[p][q];
            if (apq == 0.f) continue;
            float app = A[p][p], aqq = A[q][q];
            float tau = (aqq - app) / (2.f * apq);
            float t = ((tau >= 0.f) ? 1.f : -1.f) / (fabsf(tau) + sqrtf(1.f + tau * tau));
            float c = rsqrtf(1.f + t * t);
            float sn = t * c;
            float tau2 = sn / (1.f + c);
            A[p][p] = app - t * apq;
            A[q][q] = aqq + t * apq;
            A[p][q] = 0.f; A[q][p] = 0.f;
            int k = 3 - p - q;
            float akp = A[k][p], akq = A[k][q];
            A[k][p] = akp - sn * (akq + tau2 * akp);
            A[p][k] = A[k][p];
            A[k][q] = akq + sn * (akp - tau2 * akq);
            A[q][k] = A[k][q];
#pragma unroll
            for (int kk = 0; kk < 3; kk++) {
                float vkp = V[kk][p], vkq = V[kk][q];
                V[kk][p] = vkp - sn * (vkq + tau2 * vkp);
                V[kk][q] = vkq + sn * (vkp - tau2 * vkq);
            }
        }
    }

    // sort eigenvalues descending (columns of V follow)
    float lam[3] = {A[0][0], A[1][1], A[2][2]};
#pragma unroll
    for (int i = 0; i < 2; i++)
#pragma unroll
        for (int j = 0; j < 2 - i; j++) {
            if (lam[j] < lam[j + 1]) {
                float tl = lam[j]; lam[j] = lam[j + 1]; lam[j + 1] = tl;
#pragma unroll
                for (int k = 0; k < 3; k++) {
                    float tv = V[k][j]; V[k][j] = V[k][j + 1]; V[k][j + 1] = tv;
                }
            }
        }

    // make det(V) = +1 (flip last column if needed)
    float detV = V[0][0] * (V[1][1] * V[2][2] - V[1][2] * V[2][1])
               - V[0][1] * (V[1][0] * V[2][2] - V[1][2] * V[2][0])
               + V[0][2] * (V[1][0] * V[2][1] - V[1][1] * V[2][0]);
    if (detV < 0.f) {
        V[0][2] = -V[0][2]; V[1][2] = -V[1][2]; V[2][2] = -V[2][2];
    }

    // u0 = normalize(H v0); u1 = normalize(H v1 orthogonalized vs u0); u2 = u0 x u1
    float u0[3], u1[3], u2[3];
    {
        float t0[3], t1[3];
#pragma unroll
        for (int i = 0; i < 3; i++) {
            t0[i] = H[i][0] * V[0][0] + H[i][1] * V[1][0] + H[i][2] * V[2][0];
            t1[i] = H[i][0] * V[0][1] + H[i][1] * V[1][1] + H[i][2] * V[2][1];
        }
        float n0 = rsqrtf(fmaxf(t0[0]*t0[0] + t0[1]*t0[1] + t0[2]*t0[2], 1e-30f));
#pragma unroll
        for (int i = 0; i < 3; i++) u0[i] = t0[i] * n0;
        float dot = u0[0]*t1[0] + u0[1]*t1[1] + u0[2]*t1[2];
#pragma unroll
        for (int i = 0; i < 3; i++) t1[i] -= dot * u0[i];
        float n1 = rsqrtf(fmaxf(t1[0]*t1[0] + t1[1]*t1[1] + t1[2]*t1[2], 1e-30f));
#pragma unroll
        for (int i = 0; i < 3; i++) u1[i] = t1[i] * n1;
        u2[0] = u0[1]*u1[2] - u0[2]*u1[1];
        u2[1] = u0[2]*u1[0] - u0[0]*u1[2];
        u2[2] = u0[0]*u1[1] - u0[1]*u1[0];
    }

    // R = U V^T  (det = +1 by construction; equals Kabsch optimum)
    float R[3][3];
#pragma unroll
    for (int i = 0; i < 3; i++) {
        float ui0 = u0[i], ui1 = u1[i], ui2 = u2[i];
#pragma unroll
        for (int j = 0; j < 3; j++)
            R[i][j] = ui0 * V[j][0] + ui1 * V[j][1] + ui2 * V[j][2];
    }

    float tt[3];
#pragma unroll
    for (int i = 0; i < 3; i++)
        tt[i] = R[i][0] * mum[0] + R[i][1] * mum[1] + R[i][2] * mum[2] - muy[i];

    float T[4][4];
#pragma unroll
    for (int i = 0; i < 3; i++) {
#pragma unroll
        for (int j = 0; j < 3; j++) T[i][j] = R[i][j];
        T[i][3] = -tt[i];
    }
    T[3][0] = 0.f; T[3][1] = 0.f; T[3][2] = 0.f; T[3][3] = 1.f;

    float Tsv[4][4];
#pragma unroll
    for (int i = 0; i < 4; i++)
#pragma unroll
        for (int j = 0; j < 4; j++) Tsv[i][j] = tsv_in[i * 4 + j];

    float Tinv[4][4];
#pragma unroll
    for (int i = 0; i < 3; i++) {
#pragma unroll
        for (int j = 0; j < 3; j++) Tinv[i][j] = Tsv[j][i];
        Tinv[i][3] = -(Tsv[0][i] * Tsv[0][3] + Tsv[1][i] * Tsv[1][3] + Tsv[2][i] * Tsv[2][3]);
    }
    Tinv[3][0] = 0.f; Tinv[3][1] = 0.f; Tinv[3][2] = 0.f; Tinv[3][3] = 1.f;

    float M1[4][4];
#pragma unroll
    for (int i = 0; i < 4; i++)
#pragma unroll
        for (int j = 0; j < 4; j++) {
            float t = 0.f;
#pragma unroll
            for (int k = 0; k < 4; k++) t += Tinv[i][k] * T[k][j];
            M1[i][j] = t;
        }
    float* ob = tout + b * 16;
#pragma unroll
    for (int i = 0; i < 4; i++)
#pragma unroll
        for (int j = 0; j < 4; j++) {
            float t = 0.f;
#pragma unroll
            for (int k = 0; k < 4; k++) t += M1[i][k] * Tsv[k][j];
            ob[i * 4 + j] = t;
        }
}

// ---------------------------------------------------------------------------
// Stage 3: fill SCALED Q (B,13,13). One block per batch.
// ---------------------------------------------------------------------------
__device__ __forceinline__ int sym6(int a, int c) {
    if (a > c) { int t = a; a = c; c = t; }
    return (a == 0) ? c : (a == 1) ? (2 + c) : 5;
}

__global__ __launch_bounds__(192) void q_kernel(float* __restrict__ qout)
{
    int b = blockIdx.x;
    int t = threadIdx.x;
    __shared__ float ss[NSUM];
    __shared__ float sinv;
    if (t < NSUM) ss[t] = g_sums[b * NSUM + t];
    if (t == NSUM) sinv = g_inv_scale;
    __syncthreads();

    if (t < 169) {
        float val = 0.f;
        int i = t / 13, j = t % 13;
        if (i == 0 && j == 0) {
            val = 0.f;
        } else if (i == 0 && j <= 9) {
            val = -ss[6 + (j - 1)];
        } else if (i == 0) {
            val = ss[18 + (j - 10)];
        } else if (j == 0 && i <= 9) {
            val = -ss[6 + (i - 1)];
        } else if (j == 0) {
            val = ss[18 + (i - 10)];
        } else if (i <= 9 && j <= 9) {
            int a = (i - 1) / 3, r = (i - 1) % 3;
            int bb = (j - 1) / 3, c = (j - 1) % 3;
            if (r == c) val = ss[sym6(a, bb)];
        } else if (i <= 9) {
            int a = (i - 1) / 3, r = (i - 1) % 3, c = j - 10;
            if (r == c) val = -ss[15 + a];
        } else if (j <= 9) {
            int a = (j - 1) / 3, r = (j - 1) % 3, c = i - 10;
            if (r == c) val = -ss[15 + a];
        } else {
            if (i == j) val = ss[21];
        }
        qout[b * 169 + t] = val * sinv;
    }
}

// ---------------------------------------------------------------------------
extern "C" void kernel_launch(void* const* d_in, const int* in_sizes, int n_in,
                              void* d_out, int out_size)
{
    const float* src = (const float*)d_in[0];
    const float* trg = (const float*)d_in[1];
    const float* w   = (const float*)d_in[2];
    const float* tsv = (const float*)d_in[3];
    float* out  = (float*)d_out;
    float* tout = out;                 // (B,4,4) = 4096 floats
    float* qout = out + BB * 16;       // (B,13,13) = 43264 floats

    reduce_kernel<<<BB * SPLIT, 128>>>(src, trg, w);
    pose_kernel<<<1, 256>>>(tsv, tout);
    q_kernel<<<BB, 192>>>(qout);
}

// round 6
// speedup vs baseline: 2.8235x; 2.8235x over previous
#include <cuda_runtime.h>
#include <math.h>

#define BB 256
#define NN 2048
#define NSUM 22   // M(6 sym), C(9), mw(3), yw(3), wsum(1)

// scratch (no allocations allowed)
__device__ float g_sums[BB * NSUM];
__device__ float g_sq[BB];

// ---------------------------------------------------------------------------
// Kernel A: per-batch weighted sums over N + per-batch Q-norm^2.
// One block per batch, 256 threads, float4 loads (2 iters/thread).
// sums layout: [0..5]=M(00,01,02,11,12,22), [6..14]=C[i][j] (i=m idx, j=y idx),
//              [15..17]=mw, [18..20]=yw, [21]=wsum
// ---------------------------------------------------------------------------
__global__ __launch_bounds__(256) void reduce_kernel(
    const float* __restrict__ src, const float* __restrict__ trg,
    const float* __restrict__ w)
{
    int b = blockIdx.x;
    const int NV = NN / 4;  // 512 float4 per row
    const float4* m0 = (const float4*)(src + (size_t)b * 4 * NN);
    const float4* m1 = m0 + NV;
    const float4* m2 = m0 + 2 * NV;
    const float4* y0 = (const float4*)(trg + (size_t)b * 4 * NN);
    const float4* y1 = y0 + NV;
    const float4* y2 = y0 + 2 * NV;
    const float4* wp = (const float4*)(w + (size_t)b * NN);

    float acc[NSUM];
#pragma unroll
    for (int k = 0; k < NSUM; k++) acc[k] = 0.f;

#pragma unroll 2
    for (int n = threadIdx.x; n < NV; n += 256) {
        float4 wv4 = __ldg(wp + n);
        float4 a04 = __ldg(m0 + n), a14 = __ldg(m1 + n), a24 = __ldg(m2 + n);
        float4 c04 = __ldg(y0 + n), c14 = __ldg(y1 + n), c24 = __ldg(y2 + n);
        const float* wvp = &wv4.x;
        const float* a0p = &a04.x; const float* a1p = &a14.x; const float* a2p = &a24.x;
        const float* c0p = &c04.x; const float* c1p = &c14.x; const float* c2p = &c24.x;
#pragma unroll
        for (int l = 0; l < 4; l++) {
            float wv = wvp[l];
            float a0 = a0p[l], a1 = a1p[l], a2 = a2p[l];
            float c0 = c0p[l], c1 = c1p[l], c2 = c2p[l];
            float w0 = wv * a0, w1 = wv * a1, w2 = wv * a2;
            acc[0]  += w0 * a0; acc[1]  += w0 * a1; acc[2]  += w0 * a2;
            acc[3]  += w1 * a1; acc[4]  += w1 * a2; acc[5]  += w2 * a2;
            acc[6]  += w0 * c0; acc[7]  += w0 * c1; acc[8]  += w0 * c2;
            acc[9]  += w1 * c0; acc[10] += w1 * c1; acc[11] += w1 * c2;
            acc[12] += w2 * c0; acc[13] += w2 * c1; acc[14] += w2 * c2;
            acc[15] += w0;      acc[16] += w1;      acc[17] += w2;
            acc[18] += wv * c0; acc[19] += wv * c1; acc[20] += wv * c2;
            acc[21] += wv;
        }
    }

    // warp reduce all 22
#pragma unroll
    for (int k = 0; k < NSUM; k++)
#pragma unroll
        for (int off = 16; off > 0; off >>= 1)
            acc[k] += __shfl_xor_sync(0xFFFFFFFFu, acc[k], off);

    __shared__ float sm[8][NSUM];
    __shared__ float sfin[NSUM];
    int wid = threadIdx.x >> 5, lane = threadIdx.x & 31;
    if (lane == 0)
#pragma unroll
        for (int k = 0; k < NSUM; k++) sm[wid][k] = acc[k];
    __syncthreads();
    if (threadIdx.x < NSUM) {
        float s = 0.f;
#pragma unroll
        for (int ww = 0; ww < 8; ww++) s += sm[ww][threadIdx.x];
        g_sums[b * NSUM + threadIdx.x] = s;
        sfin[threadIdx.x] = s;
    }
    __syncthreads();
    if (threadIdx.x == 0) {
        const float* s = sfin;
        float nq = 3.f * (s[0]*s[0] + s[3]*s[3] + s[5]*s[5])
                 + 6.f * (s[1]*s[1] + s[2]*s[2] + s[4]*s[4]);
#pragma unroll
        for (int k = 6; k < 15; k++) nq += 2.f * s[k] * s[k];
#pragma unroll
        for (int k = 15; k < 18; k++) nq += 6.f * s[k] * s[k];
#pragma unroll
        for (int k = 18; k < 21; k++) nq += 2.f * s[k] * s[k];
        nq += 3.f * s[21] * s[21];
        g_sq[b] = nq;
    }
}

// ---------------------------------------------------------------------------
// Kernel B (fused): per-block redundant global-norm reduce + scaled Q fill +
// one-thread-per-block pose solve. 256 blocks x 256 threads.
// ---------------------------------------------------------------------------
__device__ __forceinline__ int sym6(int a, int c) {
    if (a > c) { int t = a; a = c; c = t; }
    return (a == 0) ? c : (a == 1) ? (2 + c) : 5;
}

__global__ __launch_bounds__(256) void fused_kernel(
    const float* __restrict__ tsv_in, float* __restrict__ tout,
    float* __restrict__ qout)
{
    int b = blockIdx.x;
    int t = threadIdx.x;

    __shared__ float ss[NSUM];
    __shared__ float smq[8];
    __shared__ float s_inv;

    if (t < NSUM) ss[t] = g_sums[b * NSUM + t];

    // global norm: every block reduces all 256 g_sq values (deterministic,
    // identical result in every block)
    float v = g_sq[t];
#pragma unroll
    for (int off = 16; off > 0; off >>= 1)
        v += __shfl_xor_sync(0xFFFFFFFFu, v, off);
    int wid = t >> 5, lane = t & 31;
    if (lane == 0) smq[wid] = v;
    __syncthreads();
    if (t == 0) {
        float tot = 0.f;
#pragma unroll
        for (int ww = 0; ww < 8; ww++) tot += smq[ww];
        float x = rsqrtf(tot);
        x = x * (1.5f - 0.5f * tot * x * x);  // Newton refine
        s_inv = x;
    }
    __syncthreads();
    float sinv = s_inv;

    // ---- Q fill (threads 0..168) ----
    if (t < 169) {
        float val = 0.f;
        int i = t / 13, j = t % 13;
        if (i == 0 && j == 0) {
            val = 0.f;
        } else if (i == 0 && j <= 9) {
            val = -ss[6 + (j - 1)];
        } else if (i == 0) {
            val = ss[18 + (j - 10)];
        } else if (j == 0 && i <= 9) {
            val = -ss[6 + (i - 1)];
        } else if (j == 0) {
            val = ss[18 + (i - 10)];
        } else if (i <= 9 && j <= 9) {
            int a = (i - 1) / 3, r = (i - 1) % 3;
            int bb2 = (j - 1) / 3, c = (j - 1) % 3;
            if (r == c) val = ss[sym6(a, bb2)];
        } else if (i <= 9) {
            int a = (i - 1) / 3, r = (i - 1) % 3, c = j - 10;
            if (r == c) val = -ss[15 + a];
        } else if (j <= 9) {
            int a = (j - 1) / 3, r = (j - 1) % 3, c = i - 10;
            if (r == c) val = -ss[15 + a];
        } else {
            if (i == j) val = ss[21];
        }
        qout[b * 169 + t] = val * sinv;
    }

    // ---- pose solve: one thread per block (thread 192, its own warp) ----
    if (t == 192) {
        const float* s = ss;
        float inv_ws = 1.f / s[21];
        float mw[3] = {s[15], s[16], s[17]};
        float yw[3] = {s[18], s[19], s[20]};

        // H = C^T - yw mw^T / ws (C[i][j] = s[6+3i+j], i=m idx, j=y idx)
        float H[3][3];
#pragma unroll
        for (int i = 0; i < 3; i++)
#pragma unroll
            for (int j = 0; j < 3; j++)
                H[i][j] = s[6 + 3 * j + i] - yw[i] * mw[j] * inv_ws;

        float mum[3], muy[3];
#pragma unroll
        for (int i = 0; i < 3; i++) { mum[i] = mw[i] * inv_ws; muy[i] = yw[i] * inv_ws; }

        // A = H^T H
        float A[3][3];
#pragma unroll
        for (int i = 0; i < 3; i++)
#pragma unroll
            for (int j = 0; j < 3; j++) {
                float tv = 0.f;
#pragma unroll
                for (int k = 0; k < 3; k++) tv += H[k][i] * H[k][j];
                A[i][j] = tv;
            }

        // Jacobi eigendecomposition: A = V L V^T
        float V[3][3] = {{1,0,0},{0,1,0},{0,0,1}};
        for (int sweep = 0; sweep < 6; sweep++) {
#pragma unroll
            for (int r = 0; r < 3; r++) {
                int p = (r == 2) ? 1 : 0;
                int q = (r == 0) ? 1 : 2;
                float apq = A[p][q];
                if (apq == 0.f) continue;
                float app = A[p][p], aqq = A[q][q];
                float tau = (aqq - app) / (2.f * apq);
                float tt2 = ((tau >= 0.f) ? 1.f : -1.f) / (fabsf(tau) + sqrtf(1.f + tau * tau));
                float c = rsqrtf(1.f + tt2 * tt2);
                float sn = tt2 * c;
                float tau2 = sn / (1.f + c);
                A[p][p] = app - tt2 * apq;
                A[q][q] = aqq + tt2 * apq;
                A[p][q] = 0.f; A[q][p] = 0.f;
                int k = 3 - p - q;
                float akp = A[k][p], akq = A[k][q];
                A[k][p] = akp - sn * (akq + tau2 * akp);
                A[p][k] = A[k][p];
                A[k][q] = akq + sn * (akp - tau2 * akq);
                A[q][k] = A[k][q];
#pragma unroll
                for (int kk = 0; kk < 3; kk++) {
                    float vkp = V[kk][p], vkq = V[kk][q];
                    V[kk][p] = vkp - sn * (vkq + tau2 * vkp);
                    V[kk][q] = vkq + sn * (vkp - tau2 * vkq);
                }
            }
        }

        // sort eigenvalues descending
        float lam[3] = {A[0][0], A[1][1], A[2][2]};
#pragma unroll
        for (int i = 0; i < 2; i++)
#pragma unroll
            for (int j = 0; j < 2 - i; j++) {
                if (lam[j] < lam[j + 1]) {
                    float tl = lam[j]; lam[j] = lam[j + 1]; lam[j + 1] = tl;
#pragma unroll
                    for (int k = 0; k < 3; k++) {
                        float tv = V[k][j]; V[k][j] = V[k][j + 1]; V[k][j + 1] = tv;
                    }
                }
            }

        // det(V) = +1
        float detV = V[0][0] * (V[1][1] * V[2][2] - V[1][2] * V[2][1])
                   - V[0][1] * (V[1][0] * V[2][2] - V[1][2] * V[2][0])
                   + V[0][2] * (V[1][0] * V[2][1] - V[1][1] * V[2][0]);
        if (detV < 0.f) {
            V[0][2] = -V[0][2]; V[1][2] = -V[1][2]; V[2][2] = -V[2][2];
        }

        // u0 = normalize(H v0); u1 = normalize((H v1) perp u0); u2 = u0 x u1
        float u0[3], u1[3], u2[3];
        {
            float t0[3], t1[3];
#pragma unroll
            for (int i = 0; i < 3; i++) {
                t0[i] = H[i][0] * V[0][0] + H[i][1] * V[1][0] + H[i][2] * V[2][0];
                t1[i] = H[i][0] * V[0][1] + H[i][1] * V[1][1] + H[i][2] * V[2][1];
            }
            float n0 = rsqrtf(fmaxf(t0[0]*t0[0] + t0[1]*t0[1] + t0[2]*t0[2], 1e-30f));
#pragma unroll
            for (int i = 0; i < 3; i++) u0[i] = t0[i] * n0;
            float dot = u0[0]*t1[0] + u0[1]*t1[1] + u0[2]*t1[2];
#pragma unroll
            for (int i = 0; i < 3; i++) t1[i] -= dot * u0[i];
            float n1 = rsqrtf(fmaxf(t1[0]*t1[0] + t1[1]*t1[1] + t1[2]*t1[2], 1e-30f));
#pragma unroll
            for (int i = 0; i < 3; i++) u1[i] = t1[i] * n1;
            u2[0] = u0[1]*u1[2] - u0[2]*u1[1];
            u2[1] = u0[2]*u1[0] - u0[0]*u1[2];
            u2[2] = u0[0]*u1[1] - u0[1]*u1[0];
        }

        // R = U V^T
        float R[3][3];
#pragma unroll
        for (int i = 0; i < 3; i++) {
            float ui0 = u0[i], ui1 = u1[i], ui2 = u2[i];
#pragma unroll
            for (int j = 0; j < 3; j++)
                R[i][j] = ui0 * V[j][0] + ui1 * V[j][1] + ui2 * V[j][2];
        }

        float tt[3];
#pragma unroll
        for (int i = 0; i < 3; i++)
            tt[i] = R[i][0] * mum[0] + R[i][1] * mum[1] + R[i][2] * mum[2] - muy[i];

        float T[4][4];
#pragma unroll
        for (int i = 0; i < 3; i++) {
#pragma unroll
            for (int j = 0; j < 3; j++) T[i][j] = R[i][j];
            T[i][3] = -tt[i];
        }
        T[3][0] = 0.f; T[3][1] = 0.f; T[3][2] = 0.f; T[3][3] = 1.f;

        float Tsv[4][4];
#pragma unroll
        for (int i = 0; i < 4; i++)
#pragma unroll
            for (int j = 0; j < 4; j++) Tsv[i][j] = tsv_in[i * 4 + j];

        float Tinv[4][4];
#pragma unroll
        for (int i = 0; i < 3; i++) {
#pragma unroll
            for (int j = 0; j < 3; j++) Tinv[i][j] = Tsv[j][i];
            Tinv[i][3] = -(Tsv[0][i] * Tsv[0][3] + Tsv[1][i] * Tsv[1][3] + Tsv[2][i] * Tsv[2][3]);
        }
        Tinv[3][0] = 0.f; Tinv[3][1] = 0.f; Tinv[3][2] = 0.f; Tinv[3][3] = 1.f;

        float M1[4][4];
#pragma unroll
        for (int i = 0; i < 4; i++)
#pragma unroll
            for (int j = 0; j < 4; j++) {
                float tv = 0.f;
#pragma unroll
                for (int k = 0; k < 4; k++) tv += Tinv[i][k] * T[k][j];
                M1[i][j] = tv;
            }
        float* ob = tout + b * 16;
#pragma unroll
        for (int i = 0; i < 4; i++)
#pragma unroll
            for (int j = 0; j < 4; j++) {
                float tv = 0.f;
#pragma unroll
                for (int k = 0; k < 4; k++) tv += M1[i][k] * Tsv[k][j];
                ob[i * 4 + j] = tv;
            }
    }
}

// ---------------------------------------------------------------------------
extern "C" void kernel_launch(void* const* d_in, const int* in_sizes, int n_in,
                              void* d_out, int out_size)
{
    const float* src = (const float*)d_in[0];
    const float* trg = (const float*)d_in[1];
    const float* w   = (const float*)d_in[2];
    const float* tsv = (const float*)d_in[3];
    float* out  = (float*)d_out;
    float* tout = out;                 // (B,4,4) = 4096 floats
    float* qout = out + BB * 16;       // (B,13,13) = 43264 floats

    reduce_kernel<<<BB, 256>>>(src, trg, w);
    fused_kernel<<<BB, 256>>>(tsv, tout, qout);
}

// round 7
// speedup vs baseline: 2.8586x; 1.0124x over previous
#include <cuda_runtime.h>
#include <math.h>

#define BB 256
#define NN 2048
#define NSUM 22   // M(6 sym), C(9), mw(3), yw(3), wsum(1)

// scratch (no allocations allowed)
__device__ float g_sums[BB * NSUM];
__device__ float g_sq[BB];

// ---------------------------------------------------------------------------
// Kernel A: per-batch weighted sums over N + per-batch Q-norm^2.
// One block per batch, 256 threads, float4 loads (2 iters/thread).
// sums layout: [0..5]=M(00,01,02,11,12,22), [6..14]=C[i][j] (i=m idx, j=y idx),
//              [15..17]=mw, [18..20]=yw, [21]=wsum
// ---------------------------------------------------------------------------
__global__ __launch_bounds__(256) void reduce_kernel(
    const float* __restrict__ src, const float* __restrict__ trg,
    const float* __restrict__ w)
{
    int b = blockIdx.x;
    const int NV = NN / 4;  // 512 float4 per row
    const float4* m0 = (const float4*)(src + (size_t)b * 4 * NN);
    const float4* m1 = m0 + NV;
    const float4* m2 = m0 + 2 * NV;
    const float4* y0 = (const float4*)(trg + (size_t)b * 4 * NN);
    const float4* y1 = y0 + NV;
    const float4* y2 = y0 + 2 * NV;
    const float4* wp = (const float4*)(w + (size_t)b * NN);

    float acc[NSUM];
#pragma unroll
    for (int k = 0; k < NSUM; k++) acc[k] = 0.f;

#pragma unroll 2
    for (int n = threadIdx.x; n < NV; n += 256) {
        float4 wv4 = __ldg(wp + n);
        float4 a04 = __ldg(m0 + n), a14 = __ldg(m1 + n), a24 = __ldg(m2 + n);
        float4 c04 = __ldg(y0 + n), c14 = __ldg(y1 + n), c24 = __ldg(y2 + n);
        const float* wvp = &wv4.x;
        const float* a0p = &a04.x; const float* a1p = &a14.x; const float* a2p = &a24.x;
        const float* c0p = &c04.x; const float* c1p = &c14.x; const float* c2p = &c24.x;
#pragma unroll
        for (int l = 0; l < 4; l++) {
            float wv = wvp[l];
            float a0 = a0p[l], a1 = a1p[l], a2 = a2p[l];
            float c0 = c0p[l], c1 = c1p[l], c2 = c2p[l];
            float w0 = wv * a0, w1 = wv * a1, w2 = wv * a2;
            acc[0]  += w0 * a0; acc[1]  += w0 * a1; acc[2]  += w0 * a2;
            acc[3]  += w1 * a1; acc[4]  += w1 * a2; acc[5]  += w2 * a2;
            acc[6]  += w0 * c0; acc[7]  += w0 * c1; acc[8]  += w0 * c2;
            acc[9]  += w1 * c0; acc[10] += w1 * c1; acc[11] += w1 * c2;
            acc[12] += w2 * c0; acc[13] += w2 * c1; acc[14] += w2 * c2;
            acc[15] += w0;      acc[16] += w1;      acc[17] += w2;
            acc[18] += wv * c0; acc[19] += wv * c1; acc[20] += wv * c2;
            acc[21] += wv;
        }
    }

    // warp reduce all 22
#pragma unroll
    for (int k = 0; k < NSUM; k++)
#pragma unroll
        for (int off = 16; off > 0; off >>= 1)
            acc[k] += __shfl_xor_sync(0xFFFFFFFFu, acc[k], off);

    __shared__ float sm[8][NSUM];
    __shared__ float sfin[NSUM];
    int wid = threadIdx.x >> 5, lane = threadIdx.x & 31;
    if (lane == 0)
#pragma unroll
        for (int k = 0; k < NSUM; k++) sm[wid][k] = acc[k];
    __syncthreads();
    if (threadIdx.x < NSUM) {
        float s = 0.f;
#pragma unroll
        for (int ww = 0; ww < 8; ww++) s += sm[ww][threadIdx.x];
        g_sums[b * NSUM + threadIdx.x] = s;
        sfin[threadIdx.x] = s;
    }
    __syncthreads();
    if (threadIdx.x == 0) {
        const float* s = sfin;
        float nq = 3.f * (s[0]*s[0] + s[3]*s[3] + s[5]*s[5])
                 + 6.f * (s[1]*s[1] + s[2]*s[2] + s[4]*s[4]);
#pragma unroll
        for (int k = 6; k < 15; k++) nq += 2.f * s[k] * s[k];
#pragma unroll
        for (int k = 15; k < 18; k++) nq += 6.f * s[k] * s[k];
#pragma unroll
        for (int k = 18; k < 21; k++) nq += 2.f * s[k] * s[k];
        nq += 3.f * s[21] * s[21];
        g_sq[b] = nq;
    }
}

// ---------------------------------------------------------------------------
// Pose solve for one batch from its 22 sums. Short-chain fp32:
// fast divisions, branchless Jacobi rotations, robust U construction.
// ---------------------------------------------------------------------------
__device__ void solve_pose(const float* __restrict__ s,
                           const float* __restrict__ tsv_in,
                           float* __restrict__ ob)
{
    float inv_ws = __fdividef(1.f, s[21]);
    float mw[3] = {s[15], s[16], s[17]};
    float yw[3] = {s[18], s[19], s[20]};

    // H = C^T - yw mw^T / ws (C[i][j] = s[6+3i+j], i=m idx, j=y idx)
    float H[3][3];
#pragma unroll
    for (int i = 0; i < 3; i++)
#pragma unroll
        for (int j = 0; j < 3; j++)
            H[i][j] = s[6 + 3 * j + i] - yw[i] * mw[j] * inv_ws;

    float mum[3], muy[3];
#pragma unroll
    for (int i = 0; i < 3; i++) { mum[i] = mw[i] * inv_ws; muy[i] = yw[i] * inv_ws; }

    // A = H^T H (symmetric)
    float A[3][3];
#pragma unroll
    for (int i = 0; i < 3; i++)
#pragma unroll
        for (int j = 0; j < 3; j++) {
            float tv = 0.f;
#pragma unroll
            for (int k = 0; k < 3; k++) tv += H[k][i] * H[k][j];
            A[i][j] = tv;
        }

    // Jacobi eigendecomposition: A = V L V^T (branchless rotations)
    float V[3][3] = {{1,0,0},{0,1,0},{0,0,1}};
    for (int sweep = 0; sweep < 5; sweep++) {
#pragma unroll
        for (int r = 0; r < 3; r++) {
            int p = (r == 2) ? 1 : 0;
            int q = (r == 0) ? 1 : 2;
            float apq = A[p][q];
            float app = A[p][p], aqq = A[q][q];
            // apq == 0 -> tau = huge -> t = 0 -> exact identity rotation
            float tau = (apq == 0.f) ? 3.4e38f : __fdividef(aqq - app, 2.f * apq);
            float t = __fdividef((tau >= 0.f) ? 1.f : -1.f,
                                 fabsf(tau) + sqrtf(1.f + tau * tau));
            float c = rsqrtf(1.f + t * t);
            float sn = t * c;
            float tau2 = __fdividef(sn, 1.f + c);
            A[p][p] = app - t * apq;
            A[q][q] = aqq + t * apq;
            A[p][q] = 0.f; A[q][p] = 0.f;
            int k = 3 - p - q;
            float akp = A[k][p], akq = A[k][q];
            A[k][p] = akp - sn * (akq + tau2 * akp);
            A[p][k] = A[k][p];
            A[k][q] = akq + sn * (akp - tau2 * akq);
            A[q][k] = A[k][q];
#pragma unroll
            for (int kk = 0; kk < 3; kk++) {
                float vkp = V[kk][p], vkq = V[kk][q];
                V[kk][p] = vkp - sn * (vkq + tau2 * vkp);
                V[kk][q] = vkq + sn * (vkp - tau2 * vkq);
            }
        }
    }

    // sort eigenvalues descending (columns of V follow)
    float lam[3] = {A[0][0], A[1][1], A[2][2]};
#pragma unroll
    for (int i = 0; i < 2; i++)
#pragma unroll
        for (int j = 0; j < 2 - i; j++) {
            if (lam[j] < lam[j + 1]) {
                float tl = lam[j]; lam[j] = lam[j + 1]; lam[j + 1] = tl;
#pragma unroll
                for (int k = 0; k < 3; k++) {
                    float tv = V[k][j]; V[k][j] = V[k][j + 1]; V[k][j + 1] = tv;
                }
            }
        }

    // det(V) = +1
    float detV = V[0][0] * (V[1][1] * V[2][2] - V[1][2] * V[2][1])
               - V[0][1] * (V[1][0] * V[2][2] - V[1][2] * V[2][0])
               + V[0][2] * (V[1][0] * V[2][1] - V[1][1] * V[2][0]);
    float flip = (detV < 0.f) ? -1.f : 1.f;
    V[0][2] *= flip; V[1][2] *= flip; V[2][2] *= flip;

    // u0 = normalize(H v0); u1 = normalize((H v1) perp u0); u2 = u0 x u1
    float u0[3], u1[3], u2[3];
    {
        float t0[3], t1[3];
#pragma unroll
        for (int i = 0; i < 3; i++) {
            t0[i] = H[i][0] * V[0][0] + H[i][1] * V[1][0] + H[i][2] * V[2][0];
            t1[i] = H[i][0] * V[0][1] + H[i][1] * V[1][1] + H[i][2] * V[2][1];
        }
        float n0 = rsqrtf(fmaxf(t0[0]*t0[0] + t0[1]*t0[1] + t0[2]*t0[2], 1e-30f));
#pragma unroll
        for (int i = 0; i < 3; i++) u0[i] = t0[i] * n0;
        float dot = u0[0]*t1[0] + u0[1]*t1[1] + u0[2]*t1[2];
#pragma unroll
        for (int i = 0; i < 3; i++) t1[i] -= dot * u0[i];
        float n1 = rsqrtf(fmaxf(t1[0]*t1[0] + t1[1]*t1[1] + t1[2]*t1[2], 1e-30f));
#pragma unroll
        for (int i = 0; i < 3; i++) u1[i] = t1[i] * n1;
        u2[0] = u0[1]*u1[2] - u0[2]*u1[1];
        u2[1] = u0[2]*u1[0] - u0[0]*u1[2];
        u2[2] = u0[0]*u1[1] - u0[1]*u1[0];
    }

    // R = U V^T
    float R[3][3];
#pragma unroll
    for (int i = 0; i < 3; i++) {
        float ui0 = u0[i], ui1 = u1[i], ui2 = u2[i];
#pragma unroll
        for (int j = 0; j < 3; j++)
            R[i][j] = ui0 * V[j][0] + ui1 * V[j][1] + ui2 * V[j][2];
    }

    float tt[3];
#pragma unroll
    for (int i = 0; i < 3; i++)
        tt[i] = R[i][0] * mum[0] + R[i][1] * mum[1] + R[i][2] * mum[2] - muy[i];

    float T[4][4];
#pragma unroll
    for (int i = 0; i < 3; i++) {
#pragma unroll
        for (int j = 0; j < 3; j++) T[i][j] = R[i][j];
        T[i][3] = -tt[i];
    }
    T[3][0] = 0.f; T[3][1] = 0.f; T[3][2] = 0.f; T[3][3] = 1.f;

    float Tsv[4][4];
#pragma unroll
    for (int i = 0; i < 4; i++)
#pragma unroll
        for (int j = 0; j < 4; j++) Tsv[i][j] = tsv_in[i * 4 + j];

    float Tinv[4][4];
#pragma unroll
    for (int i = 0; i < 3; i++) {
#pragma unroll
        for (int j = 0; j < 3; j++) Tinv[i][j] = Tsv[j][i];
        Tinv[i][3] = -(Tsv[0][i] * Tsv[0][3] + Tsv[1][i] * Tsv[1][3] + Tsv[2][i] * Tsv[2][3]);
    }
    Tinv[3][0] = 0.f; Tinv[3][1] = 0.f; Tinv[3][2] = 0.f; Tinv[3][3] = 1.f;

    float M1[4][4];
#pragma unroll
    for (int i = 0; i < 4; i++)
#pragma unroll
        for (int j = 0; j < 4; j++) {
            float tv = 0.f;
#pragma unroll
            for (int k = 0; k < 4; k++) tv += Tinv[i][k] * T[k][j];
            M1[i][j] = tv;
        }
#pragma unroll
    for (int i = 0; i < 4; i++)
#pragma unroll
        for (int j = 0; j < 4; j++) {
            float tv = 0.f;
#pragma unroll
            for (int k = 0; k < 4; k++) tv += M1[i][k] * Tsv[k][j];
            ob[i * 4 + j] = tv;
        }
}

// ---------------------------------------------------------------------------
// Kernel B (fused): 128 blocks x 256 threads; block handles batches 2b, 2b+1.
// Per-block redundant global-norm reduce + scaled Q fill (338 entries) +
// two pose solves on adjacent lanes (SIMT-parallel, one chain latency).
// ---------------------------------------------------------------------------
__device__ __forceinline__ int sym6(int a, int c) {
    if (a > c) { int t = a; a = c; c = t; }
    return (a == 0) ? c : (a == 1) ? (2 + c) : 5;
}

__device__ __forceinline__ float q_entry(const float* __restrict__ ss, int e)
{
    int i = e / 13, j = e % 13;
    float val = 0.f;
    if (i == 0 && j == 0) {
        val = 0.f;
    } else if (i == 0 && j <= 9) {
        val = -ss[6 + (j - 1)];
    } else if (i == 0) {
        val = ss[18 + (j - 10)];
    } else if (j == 0 && i <= 9) {
        val = -ss[6 + (i - 1)];
    } else if (j == 0) {
        val = ss[18 + (i - 10)];
    } else if (i <= 9 && j <= 9) {
        int a = (i - 1) / 3, r = (i - 1) % 3;
        int bb2 = (j - 1) / 3, c = (j - 1) % 3;
        if (r == c) val = ss[sym6(a, bb2)];
    } else if (i <= 9) {
        int a = (i - 1) / 3, r = (i - 1) % 3, c = j - 10;
        if (r == c) val = -ss[15 + a];
    } else if (j <= 9) {
        int a = (j - 1) / 3, r = (j - 1) % 3, c = i - 10;
        if (r == c) val = -ss[15 + a];
    } else {
        if (i == j) val = ss[21];
    }
    return val;
}

__global__ __launch_bounds__(256) void fused_kernel(
    const float* __restrict__ tsv_in, float* __restrict__ tout,
    float* __restrict__ qout)
{
    int bb = blockIdx.x;          // 0..127
    int b0 = 2 * bb;              // first batch
    int t = threadIdx.x;

    __shared__ float ss[2][NSUM];
    __shared__ float smq[8];
    __shared__ float s_inv;

    if (t < 2 * NSUM) ss[t / NSUM][t % NSUM] = g_sums[b0 * NSUM + t];

    // global norm: every block reduces all 256 g_sq values (deterministic)
    float v = g_sq[t];
#pragma unroll
    for (int off = 16; off > 0; off >>= 1)
        v += __shfl_xor_sync(0xFFFFFFFFu, v, off);
    int wid = t >> 5, lane = t & 31;
    if (lane == 0) smq[wid] = v;
    __syncthreads();
    if (t == 0) {
        float tot = 0.f;
#pragma unroll
        for (int ww = 0; ww < 8; ww++) tot += smq[ww];
        float x = rsqrtf(tot);
        x = x * (1.5f - 0.5f * tot * x * x);  // Newton refine
        s_inv = x;
    }
    __syncthreads();
    float sinv = s_inv;

    // ---- Q fill: 338 entries for 2 batches ----
#pragma unroll
    for (int e = t; e < 338; e += 256) {
        int sub = (e >= 169) ? 1 : 0;
        int idx = e - sub * 169;
        qout[(b0 + sub) * 169 + idx] = q_entry(ss[sub], idx) * sinv;
    }

    // ---- pose: lanes 192/193 (same warp -> SIMT lockstep, one chain) ----
    if (t == 192 || t == 193) {
        int sub = t - 192;
        solve_pose(ss[sub], tsv_in, tout + (b0 + sub) * 16);
    }
}

// ---------------------------------------------------------------------------
extern "C" void kernel_launch(void* const* d_in, const int* in_sizes, int n_in,
                              void* d_out, int out_size)
{
    const float* src = (const float*)d_in[0];
    const float* trg = (const float*)d_in[1];
    const float* w   = (const float*)d_in[2];
    const float* tsv = (const float*)d_in[3];
    float* out  = (float*)d_out;
    float* tout = out;                 // (B,4,4) = 4096 floats
    float* qout = out + BB * 16;       // (B,13,13) = 43264 floats

    reduce_kernel<<<BB, 256>>>(src, trg, w);
    fused_kernel<<<BB / 2, 256>>>(tsv, tout, qout);
}

// round 8
// speedup vs baseline: 2.9313x; 1.0254x over previous
#include <cuda_runtime.h>
#include <math.h>

#define BB 256
#define NN 2048
#define NSUM 22   // M(6 sym), C(9), mw(3), yw(3), wsum(1)

// scratch (no allocations allowed)
__device__ float g_sums[BB * NSUM];
__device__ float g_sq[BB];

// ---------------------------------------------------------------------------
// Pose solve for one batch from its 22 sums. Short-chain fp32:
// half-angle Givens (no divisions in the rotation), robust U construction.
// ---------------------------------------------------------------------------
__device__ __forceinline__ void solve_pose(const float* __restrict__ s,
                                           const float* __restrict__ tsv_in,
                                           float* __restrict__ ob)
{
    float inv_ws = __fdividef(1.f, s[21]);
    float mw[3] = {s[15], s[16], s[17]};
    float yw[3] = {s[18], s[19], s[20]};

    // H = C^T - yw mw^T / ws (C[i][j] = s[6+3i+j], i=m idx, j=y idx)
    float H[3][3];
#pragma unroll
    for (int i = 0; i < 3; i++)
#pragma unroll
        for (int j = 0; j < 3; j++)
            H[i][j] = s[6 + 3 * j + i] - yw[i] * mw[j] * inv_ws;

    float mum[3], muy[3];
#pragma unroll
    for (int i = 0; i < 3; i++) { mum[i] = mw[i] * inv_ws; muy[i] = yw[i] * inv_ws; }

    // A = H^T H (symmetric)
    float A[3][3];
#pragma unroll
    for (int i = 0; i < 3; i++)
#pragma unroll
        for (int j = 0; j < 3; j++) {
            float tv = 0.f;
#pragma unroll
            for (int k = 0; k < 3; k++) tv += H[k][i] * H[k][j];
            A[i][j] = tv;
        }

    // Jacobi eigendecomposition A = V L V^T, half-angle rotations (no div).
    float V[3][3] = {{1,0,0},{0,1,0},{0,0,1}};
    for (int sweep = 0; sweep < 5; sweep++) {
#pragma unroll
        for (int r = 0; r < 3; r++) {
            int p = (r == 2) ? 1 : 0;
            int q = (r == 0) ? 1 : 2;
            float apq = A[p][q];
            float app = A[p][p], aqq = A[q][q];
            float d = app - aqq;
            float u = d * d + 4.f * apq * apq;
            float inv_r = rsqrtf(fmaxf(u, 1e-38f));
            float ratio = fabsf(d) * inv_r;                       // cos(2t) in [0,1]
            float c = sqrtf(0.5f + 0.5f * ratio);
            float sn = copysignf(sqrtf(fmaxf(0.5f - 0.5f * ratio, 0.f)), -apq * d);
            float c2 = c * c, s2 = sn * sn, cs = c * sn;
            A[p][p] = c2 * app - 2.f * cs * apq + s2 * aqq;
            A[q][q] = s2 * app + 2.f * cs * apq + c2 * aqq;
            A[p][q] = 0.f; A[q][p] = 0.f;
            int k = 3 - p - q;
            float akp = A[k][p], akq = A[k][q];
            A[k][p] = c * akp - sn * akq;  A[p][k] = A[k][p];
            A[k][q] = sn * akp + c * akq;  A[q][k] = A[k][q];
#pragma unroll
            for (int kk = 0; kk < 3; kk++) {
                float vkp = V[kk][p], vkq = V[kk][q];
                V[kk][p] = c * vkp - sn * vkq;
                V[kk][q] = sn * vkp + c * vkq;
            }
        }
    }

    // sort eigenvalues descending (columns of V follow)
    float lam[3] = {A[0][0], A[1][1], A[2][2]};
#pragma unroll
    for (int i = 0; i < 2; i++)
#pragma unroll
        for (int j = 0; j < 2 - i; j++) {
            if (lam[j] < lam[j + 1]) {
                float tl = lam[j]; lam[j] = lam[j + 1]; lam[j + 1] = tl;
#pragma unroll
                for (int k = 0; k < 3; k++) {
                    float tv = V[k][j]; V[k][j] = V[k][j + 1]; V[k][j + 1] = tv;
                }
            }
        }

    // det(V) = +1
    float detV = V[0][0] * (V[1][1] * V[2][2] - V[1][2] * V[2][1])
               - V[0][1] * (V[1][0] * V[2][2] - V[1][2] * V[2][0])
               + V[0][2] * (V[1][0] * V[2][1] - V[1][1] * V[2][0]);
    float flip = (detV < 0.f) ? -1.f : 1.f;
    V[0][2] *= flip; V[1][2] *= flip; V[2][2] *= flip;

    // u0 = normalize(H v0); u1 = normalize((H v1) perp u0); u2 = u0 x u1
    float u0[3], u1[3], u2[3];
    {
        float t0[3], t1[3];
#pragma unroll
        for (int i = 0; i < 3; i++) {
            t0[i] = H[i][0] * V[0][0] + H[i][1] * V[1][0] + H[i][2] * V[2][0];
            t1[i] = H[i][0] * V[0][1] + H[i][1] * V[1][1] + H[i][2] * V[2][1];
        }
        float n0 = rsqrtf(fmaxf(t0[0]*t0[0] + t0[1]*t0[1] + t0[2]*t0[2], 1e-30f));
#pragma unroll
        for (int i = 0; i < 3; i++) u0[i] = t0[i] * n0;
        float dot = u0[0]*t1[0] + u0[1]*t1[1] + u0[2]*t1[2];
#pragma unroll
        for (int i = 0; i < 3; i++) t1[i] -= dot * u0[i];
        float n1 = rsqrtf(fmaxf(t1[0]*t1[0] + t1[1]*t1[1] + t1[2]*t1[2], 1e-30f));
#pragma unroll
        for (int i = 0; i < 3; i++) u1[i] = t1[i] * n1;
        u2[0] = u0[1]*u1[2] - u0[2]*u1[1];
        u2[1] = u0[2]*u1[0] - u0[0]*u1[2];
        u2[2] = u0[0]*u1[1] - u0[1]*u1[0];
    }

    // R = U V^T
    float R[3][3];
#pragma unroll
    for (int i = 0; i < 3; i++) {
        float ui0 = u0[i], ui1 = u1[i], ui2 = u2[i];
#pragma unroll
        for (int j = 0; j < 3; j++)
            R[i][j] = ui0 * V[j][0] + ui1 * V[j][1] + ui2 * V[j][2];
    }

    float tt[3];
#pragma unroll
    for (int i = 0; i < 3; i++)
        tt[i] = R[i][0] * mum[0] + R[i][1] * mum[1] + R[i][2] * mum[2] - muy[i];

    float T[4][4];
#pragma unroll
    for (int i = 0; i < 3; i++) {
#pragma unroll
        for (int j = 0; j < 3; j++) T[i][j] = R[i][j];
        T[i][3] = -tt[i];
    }
    T[3][0] = 0.f; T[3][1] = 0.f; T[3][2] = 0.f; T[3][3] = 1.f;

    float Tsv[4][4];
#pragma unroll
    for (int i = 0; i < 4; i++)
#pragma unroll
        for (int j = 0; j < 4; j++) Tsv[i][j] = tsv_in[i * 4 + j];

    float Tinv[4][4];
#pragma unroll
    for (int i = 0; i < 3; i++) {
#pragma unroll
        for (int j = 0; j < 3; j++) Tinv[i][j] = Tsv[j][i];
        Tinv[i][3] = -(Tsv[0][i] * Tsv[0][3] + Tsv[1][i] * Tsv[1][3] + Tsv[2][i] * Tsv[2][3]);
    }
    Tinv[3][0] = 0.f; Tinv[3][1] = 0.f; Tinv[3][2] = 0.f; Tinv[3][3] = 1.f;

    float M1[4][4];
#pragma unroll
    for (int i = 0; i < 4; i++)
#pragma unroll
        for (int j = 0; j < 4; j++) {
            float tv = 0.f;
#pragma unroll
            for (int k = 0; k < 4; k++) tv += Tinv[i][k] * T[k][j];
            M1[i][j] = tv;
        }
#pragma unroll
    for (int i = 0; i < 4; i++)
#pragma unroll
        for (int j = 0; j < 4; j++) {
            float tv = 0.f;
#pragma unroll
            for (int k = 0; k < 4; k++) tv += M1[i][k] * Tsv[k][j];
            ob[i * 4 + j] = tv;
        }
}

// ---------------------------------------------------------------------------
// Kernel A: per-batch weighted sums + per-batch Q-norm^2 + POSE (fused).
// One block per batch, 256 threads, float4 loads.
// After the block reduction, thread 0 writes the norm partial and thread 32
// (warp 1) runs the pose solve — 256 pose chains run concurrently chip-wide.
// ---------------------------------------------------------------------------
__global__ __launch_bounds__(256) void reduce_kernel(
    const float* __restrict__ src, const float* __restrict__ trg,
    const float* __restrict__ w, const float* __restrict__ tsv,
    float* __restrict__ tout)
{
    int b = blockIdx.x;
    const int NV = NN / 4;  // 512 float4 per row
    const float4* m0 = (const float4*)(src + (size_t)b * 4 * NN);
    const float4* m1 = m0 + NV;
    const float4* m2 = m0 + 2 * NV;
    const float4* y0 = (const float4*)(trg + (size_t)b * 4 * NN);
    const float4* y1 = y0 + NV;
    const float4* y2 = y0 + 2 * NV;
    const float4* wp = (const float4*)(w + (size_t)b * NN);

    float acc[NSUM];
#pragma unroll
    for (int k = 0; k < NSUM; k++) acc[k] = 0.f;

#pragma unroll 2
    for (int n = threadIdx.x; n < NV; n += 256) {
        float4 wv4 = __ldg(wp + n);
        float4 a04 = __ldg(m0 + n), a14 = __ldg(m1 + n), a24 = __ldg(m2 + n);
        float4 c04 = __ldg(y0 + n), c14 = __ldg(y1 + n), c24 = __ldg(y2 + n);
        const float* wvp = &wv4.x;
        const float* a0p = &a04.x; const float* a1p = &a14.x; const float* a2p = &a24.x;
        const float* c0p = &c04.x; const float* c1p = &c14.x; const float* c2p = &c24.x;
#pragma unroll
        for (int l = 0; l < 4; l++) {
            float wv = wvp[l];
            float a0 = a0p[l], a1 = a1p[l], a2 = a2p[l];
            float c0 = c0p[l], c1 = c1p[l], c2 = c2p[l];
            float w0 = wv * a0, w1 = wv * a1, w2 = wv * a2;
            acc[0]  += w0 * a0; acc[1]  += w0 * a1; acc[2]  += w0 * a2;
            acc[3]  += w1 * a1; acc[4]  += w1 * a2; acc[5]  += w2 * a2;
            acc[6]  += w0 * c0; acc[7]  += w0 * c1; acc[8]  += w0 * c2;
            acc[9]  += w1 * c0; acc[10] += w1 * c1; acc[11] += w1 * c2;
            acc[12] += w2 * c0; acc[13] += w2 * c1; acc[14] += w2 * c2;
            acc[15] += w0;      acc[16] += w1;      acc[17] += w2;
            acc[18] += wv * c0; acc[19] += wv * c1; acc[20] += wv * c2;
            acc[21] += wv;
        }
    }

    // warp reduce all 22
#pragma unroll
    for (int k = 0; k < NSUM; k++)
#pragma unroll
        for (int off = 16; off > 0; off >>= 1)
            acc[k] += __shfl_xor_sync(0xFFFFFFFFu, acc[k], off);

    __shared__ float sm[8][NSUM];
    __shared__ float sfin[NSUM];
    int wid = threadIdx.x >> 5, lane = threadIdx.x & 31;
    if (lane == 0)
#pragma unroll
        for (int k = 0; k < NSUM; k++) sm[wid][k] = acc[k];
    __syncthreads();
    if (threadIdx.x < NSUM) {
        float s = 0.f;
#pragma unroll
        for (int ww = 0; ww < 8; ww++) s += sm[ww][threadIdx.x];
        g_sums[b * NSUM + threadIdx.x] = s;
        sfin[threadIdx.x] = s;
    }
    __syncthreads();

    if (threadIdx.x == 0) {
        const float* s = sfin;
        float nq = 3.f * (s[0]*s[0] + s[3]*s[3] + s[5]*s[5])
                 + 6.f * (s[1]*s[1] + s[2]*s[2] + s[4]*s[4]);
#pragma unroll
        for (int k = 6; k < 15; k++) nq += 2.f * s[k] * s[k];
#pragma unroll
        for (int k = 15; k < 18; k++) nq += 6.f * s[k] * s[k];
#pragma unroll
        for (int k = 18; k < 21; k++) nq += 2.f * s[k] * s[k];
        nq += 3.f * s[21] * s[21];
        g_sq[b] = nq;
    }

    // pose on warp 1 lane 0 — overlaps with thread 0's norm work
    if (threadIdx.x == 32) {
        solve_pose(sfin, tsv, tout + b * 16);
    }
}

// ---------------------------------------------------------------------------
// Kernel B: global-norm reduce (redundant per block, deterministic) +
// scaled Q fill. 128 blocks x 256 threads; block handles batches 2b, 2b+1.
// ---------------------------------------------------------------------------
__device__ __forceinline__ int sym6(int a, int c) {
    if (a > c) { int t = a; a = c; c = t; }
    return (a == 0) ? c : (a == 1) ? (2 + c) : 5;
}

__device__ __forceinline__ float q_entry(const float* __restrict__ ss, int e)
{
    int i = e / 13, j = e % 13;
    float val = 0.f;
    if (i == 0 && j == 0) {
        val = 0.f;
    } else if (i == 0 && j <= 9) {
        val = -ss[6 + (j - 1)];
    } else if (i == 0) {
        val = ss[18 + (j - 10)];
    } else if (j == 0 && i <= 9) {
        val = -ss[6 + (i - 1)];
    } else if (j == 0) {
        val = ss[18 + (i - 10)];
    } else if (i <= 9 && j <= 9) {
        int a = (i - 1) / 3, r = (i - 1) % 3;
        int bb2 = (j - 1) / 3, c = (j - 1) % 3;
        if (r == c) val = ss[sym6(a, bb2)];
    } else if (i <= 9) {
        int a = (i - 1) / 3, r = (i - 1) % 3, c = j - 10;
        if (r == c) val = -ss[15 + a];
    } else if (j <= 9) {
        int a = (j - 1) / 3, r = (j - 1) % 3, c = i - 10;
        if (r == c) val = -ss[15 + a];
    } else {
        if (i == j) val = ss[21];
    }
    return val;
}

__global__ __launch_bounds__(256) void q_scale_kernel(float* __restrict__ qout)
{
    int bb = blockIdx.x;          // 0..127
    int b0 = 2 * bb;
    int t = threadIdx.x;

    __shared__ float ss[2][NSUM];
    __shared__ float smq[8];
    __shared__ float s_inv;

    if (t < 2 * NSUM) ss[t / NSUM][t % NSUM] = g_sums[b0 * NSUM + t];

    // global norm: every block reduces all 256 g_sq values (deterministic)
    float v = g_sq[t];
#pragma unroll
    for (int off = 16; off > 0; off >>= 1)
        v += __shfl_xor_sync(0xFFFFFFFFu, v, off);
    int wid = t >> 5, lane = t & 31;
    if (lane == 0) smq[wid] = v;
    __syncthreads();
    if (t == 0) {
        float tot = 0.f;
#pragma unroll
        for (int ww = 0; ww < 8; ww++) tot += smq[ww];
        float x = rsqrtf(tot);
        x = x * (1.5f - 0.5f * tot * x * x);  // Newton refine
        s_inv = x;
    }
    __syncthreads();
    float sinv = s_inv;

    // Q fill: 338 entries for 2 batches
#pragma unroll
    for (int e = t; e < 338; e += 256) {
        int sub = (e >= 169) ? 1 : 0;
        int idx = e - sub * 169;
        qout[(b0 + sub) * 169 + idx] = q_entry(ss[sub], idx) * sinv;
    }
}

// ---------------------------------------------------------------------------
extern "C" void kernel_launch(void* const* d_in, const int* in_sizes, int n_in,
                              void* d_out, int out_size)
{
    const float* src = (const float*)d_in[0];
    const float* trg = (const float*)d_in[1];
    const float* w   = (const float*)d_in[2];
    const float* tsv = (const float*)d_in[3];
    float* out  = (float*)d_out;
    float* tout = out;                 // (B,4,4) = 4096 floats
    float* qout = out + BB * 16;       // (B,13,13) = 43264 floats

    reduce_kernel<<<BB, 256>>>(src, trg, w, tsv, tout);
    q_scale_kernel<<<BB / 2, 256>>>(qout);
}

// round 9
// speedup vs baseline: 3.3295x; 1.1358x over previous
#include <cuda_runtime.h>
#include <math.h>

#define BB 256
#define NN 2048
#define NSUM 22   // M(6 sym), C(9), mw(3), yw(3), wsum(1)

// scratch (no allocations allowed)
__device__ float g_sq[BB];
__device__ unsigned int g_ctr;   // zero-init; monotonic across graph replays

// ---------------------------------------------------------------------------
// Pose solve for one batch from its 22 sums. fp32, tangent-form Jacobi
// (numerically stable for small rotations), robust U construction.
// ---------------------------------------------------------------------------
__device__ void solve_pose(const float* __restrict__ s,
                           const float* __restrict__ tsv_in,
                           float* __restrict__ ob)
{
    float inv_ws = __fdividef(1.f, s[21]);
    float mw[3] = {s[15], s[16], s[17]};
    float yw[3] = {s[18], s[19], s[20]};

    // H = C^T - yw mw^T / ws (C[i][j] = s[6+3i+j], i=m idx, j=y idx)
    float H[3][3];
#pragma unroll
    for (int i = 0; i < 3; i++)
#pragma unroll
        for (int j = 0; j < 3; j++)
            H[i][j] = s[6 + 3 * j + i] - yw[i] * mw[j] * inv_ws;

    float mum[3], muy[3];
#pragma unroll
    for (int i = 0; i < 3; i++) { mum[i] = mw[i] * inv_ws; muy[i] = yw[i] * inv_ws; }

    // A = H^T H (symmetric)
    float A[3][3];
#pragma unroll
    for (int i = 0; i < 3; i++)
#pragma unroll
        for (int j = 0; j < 3; j++) {
            float tv = 0.f;
#pragma unroll
            for (int k = 0; k < 3; k++) tv += H[k][i] * H[k][j];
            A[i][j] = tv;
        }

    // Jacobi eigendecomposition: A = V L V^T (tangent form, fast divides)
    float V[3][3] = {{1,0,0},{0,1,0},{0,0,1}};
    for (int sweep = 0; sweep < 5; sweep++) {
#pragma unroll
        for (int r = 0; r < 3; r++) {
            int p = (r == 2) ? 1 : 0;
            int q = (r == 0) ? 1 : 2;
            float apq = A[p][q];
            float app = A[p][p], aqq = A[q][q];
            // apq == 0 -> tau huge -> t = 0 -> exact identity rotation
            float tau = (apq == 0.f) ? 3.4e38f : __fdividef(aqq - app, 2.f * apq);
            float t = __fdividef((tau >= 0.f) ? 1.f : -1.f,
                                 fabsf(tau) + sqrtf(1.f + tau * tau));
            float c = rsqrtf(1.f + t * t);
            float sn = t * c;
            float tau2 = __fdividef(sn, 1.f + c);
            A[p][p] = app - t * apq;
            A[q][q] = aqq + t * apq;
            A[p][q] = 0.f; A[q][p] = 0.f;
            int k = 3 - p - q;
            float akp = A[k][p], akq = A[k][q];
            A[k][p] = akp - sn * (akq + tau2 * akp);
            A[p][k] = A[k][p];
            A[k][q] = akq + sn * (akp - tau2 * akq);
            A[q][k] = A[k][q];
#pragma unroll
            for (int kk = 0; kk < 3; kk++) {
                float vkp = V[kk][p], vkq = V[kk][q];
                V[kk][p] = vkp - sn * (vkq + tau2 * vkp);
                V[kk][q] = vkq + sn * (vkp - tau2 * vkq);
            }
        }
    }

    // sort eigenvalues descending (columns of V follow)
    float lam[3] = {A[0][0], A[1][1], A[2][2]};
#pragma unroll
    for (int i = 0; i < 2; i++)
#pragma unroll
        for (int j = 0; j < 2 - i; j++) {
            if (lam[j] < lam[j + 1]) {
                float tl = lam[j]; lam[j] = lam[j + 1]; lam[j + 1] = tl;
#pragma unroll
                for (int k = 0; k < 3; k++) {
                    float tv = V[k][j]; V[k][j] = V[k][j + 1]; V[k][j + 1] = tv;
                }
            }
        }

    // det(V) = +1
    float detV = V[0][0] * (V[1][1] * V[2][2] - V[1][2] * V[2][1])
               - V[0][1] * (V[1][0] * V[2][2] - V[1][2] * V[2][0])
               + V[0][2] * (V[1][0] * V[2][1] - V[1][1] * V[2][0]);
    float flip = (detV < 0.f) ? -1.f : 1.f;
    V[0][2] *= flip; V[1][2] *= flip; V[2][2] *= flip;

    // u0 = normalize(H v0); u1 = normalize((H v1) perp u0); u2 = u0 x u1
    float u0[3], u1[3], u2[3];
    {
        float t0[3], t1[3];
#pragma unroll
        for (int i = 0; i < 3; i++) {
            t0[i] = H[i][0] * V[0][0] + H[i][1] * V[1][0] + H[i][2] * V[2][0];
            t1[i] = H[i][0] * V[0][1] + H[i][1] * V[1][1] + H[i][2] * V[2][1];
        }
        float n0 = rsqrtf(fmaxf(t0[0]*t0[0] + t0[1]*t0[1] + t0[2]*t0[2], 1e-30f));
#pragma unroll
        for (int i = 0; i < 3; i++) u0[i] = t0[i] * n0;
        float dot = u0[0]*t1[0] + u0[1]*t1[1] + u0[2]*t1[2];
#pragma unroll
        for (int i = 0; i < 3; i++) t1[i] -= dot * u0[i];
        float n1 = rsqrtf(fmaxf(t1[0]*t1[0] + t1[1]*t1[1] + t1[2]*t1[2], 1e-30f));
#pragma unroll
        for (int i = 0; i < 3; i++) u1[i] = t1[i] * n1;
        u2[0] = u0[1]*u1[2] - u0[2]*u1[1];
        u2[1] = u0[2]*u1[0] - u0[0]*u1[2];
        u2[2] = u0[0]*u1[1] - u0[1]*u1[0];
    }

    // R = U V^T
    float R[3][3];
#pragma unroll
    for (int i = 0; i < 3; i++) {
        float ui0 = u0[i], ui1 = u1[i], ui2 = u2[i];
#pragma unroll
        for (int j = 0; j < 3; j++)
            R[i][j] = ui0 * V[j][0] + ui1 * V[j][1] + ui2 * V[j][2];
    }

    float tt[3];
#pragma unroll
    for (int i = 0; i < 3; i++)
        tt[i] = R[i][0] * mum[0] + R[i][1] * mum[1] + R[i][2] * mum[2] - muy[i];

    float T[4][4];
#pragma unroll
    for (int i = 0; i < 3; i++) {
#pragma unroll
        for (int j = 0; j < 3; j++) T[i][j] = R[i][j];
        T[i][3] = -tt[i];
    }
    T[3][0] = 0.f; T[3][1] = 0.f; T[3][2] = 0.f; T[3][3] = 1.f;

    float Tsv[4][4];
#pragma unroll
    for (int i = 0; i < 4; i++)
#pragma unroll
        for (int j = 0; j < 4; j++) Tsv[i][j] = tsv_in[i * 4 + j];

    float Tinv[4][4];
#pragma unroll
    for (int i = 0; i < 3; i++) {
#pragma unroll
        for (int j = 0; j < 3; j++) Tinv[i][j] = Tsv[j][i];
        Tinv[i][3] = -(Tsv[0][i] * Tsv[0][3] + Tsv[1][i] * Tsv[1][3] + Tsv[2][i] * Tsv[2][3]);
    }
    Tinv[3][0] = 0.f; Tinv[3][1] = 0.f; Tinv[3][2] = 0.f; Tinv[3][3] = 1.f;

    float M1[4][4];
#pragma unroll
    for (int i = 0; i < 4; i++)
#pragma unroll
        for (int j = 0; j < 4; j++) {
            float tv = 0.f;
#pragma unroll
            for (int k = 0; k < 4; k++) tv += Tinv[i][k] * T[k][j];
            M1[i][j] = tv;
        }
#pragma unroll
    for (int i = 0; i < 4; i++)
#pragma unroll
        for (int j = 0; j < 4; j++) {
            float tv = 0.f;
#pragma unroll
            for (int k = 0; k < 4; k++) tv += M1[i][k] * Tsv[k][j];
            ob[i * 4 + j] = tv;
        }
}

// ---------------------------------------------------------------------------
__device__ __forceinline__ int sym6(int a, int c) {
    if (a > c) { int t = a; a = c; c = t; }
    return (a == 0) ? c : (a == 1) ? (2 + c) : 5;
}

__device__ __forceinline__ float q_entry(const float* __restrict__ ss, int e)
{
    int i = e / 13, j = e % 13;
    float val = 0.f;
    if (i == 0 && j == 0) {
        val = 0.f;
    } else if (i == 0 && j <= 9) {
        val = -ss[6 + (j - 1)];
    } else if (i == 0) {
        val = ss[18 + (j - 10)];
    } else if (j == 0 && i <= 9) {
        val = -ss[6 + (i - 1)];
    } else if (j == 0) {
        val = ss[18 + (i - 10)];
    } else if (i <= 9 && j <= 9) {
        int a = (i - 1) / 3, r = (i - 1) % 3;
        int bb2 = (j - 1) / 3, c = (j - 1) % 3;
        if (r == c) val = ss[sym6(a, bb2)];
    } else if (i <= 9) {
        int a = (i - 1) / 3, r = (i - 1) % 3, c = j - 10;
        if (r == c) val = -ss[15 + a];
    } else if (j <= 9) {
        int a = (j - 1) / 3, r = (j - 1) % 3, c = i - 10;
        if (r == c) val = -ss[15 + a];
    } else {
        if (i == j) val = ss[21];
    }
    return val;
}

// ---------------------------------------------------------------------------
// SINGLE fused kernel. 256 blocks x 256 threads, __launch_bounds__(256,2)
// guarantees >= 2 blocks/SM -> all 256 blocks co-resident (148 SMs) -> the
// grid-wide ticket-spin below cannot deadlock.
//
// Phases per block b:
//   1. reduction of 22 weighted sums over N (float4 loads) -> smem sfin
//   2. warp 6 lane 0: pose solve (overlaps phases 3-4)
//      warp 0: g_sq[b] publish + fence + ticket + spin until all 256 published
//   3. warps 0-5 meet at named barrier (192 threads)
//   4. per-warp deterministic inv_scale from g_sq, Q fill (threads 0-168)
// ---------------------------------------------------------------------------
__global__ __launch_bounds__(256, 2) void fused_all(
    const float* __restrict__ src, const float* __restrict__ trg,
    const float* __restrict__ w, const float* __restrict__ tsv,
    float* __restrict__ tout, float* __restrict__ qout)
{
    int b = blockIdx.x;
    const int NV = NN / 4;  // 512 float4 per row
    const float4* m0 = (const float4*)(src + (size_t)b * 4 * NN);
    const float4* m1 = m0 + NV;
    const float4* m2 = m0 + 2 * NV;
    const float4* y0 = (const float4*)(trg + (size_t)b * 4 * NN);
    const float4* y1 = y0 + NV;
    const float4* y2 = y0 + 2 * NV;
    const float4* wp = (const float4*)(w + (size_t)b * NN);

    float acc[NSUM];
#pragma unroll
    for (int k = 0; k < NSUM; k++) acc[k] = 0.f;

#pragma unroll 2
    for (int n = threadIdx.x; n < NV; n += 256) {
        float4 wv4 = __ldg(wp + n);
        float4 a04 = __ldg(m0 + n), a14 = __ldg(m1 + n), a24 = __ldg(m2 + n);
        float4 c04 = __ldg(y0 + n), c14 = __ldg(y1 + n), c24 = __ldg(y2 + n);
        const float* wvp = &wv4.x;
        const float* a0p = &a04.x; const float* a1p = &a14.x; const float* a2p = &a24.x;
        const float* c0p = &c04.x; const float* c1p = &c14.x; const float* c2p = &c24.x;
#pragma unroll
        for (int l = 0; l < 4; l++) {
            float wv = wvp[l];
            float a0 = a0p[l], a1 = a1p[l], a2 = a2p[l];
            float c0 = c0p[l], c1 = c1p[l], c2 = c2p[l];
            float w0 = wv * a0, w1 = wv * a1, w2 = wv * a2;
            acc[0]  += w0 * a0; acc[1]  += w0 * a1; acc[2]  += w0 * a2;
            acc[3]  += w1 * a1; acc[4]  += w1 * a2; acc[5]  += w2 * a2;
            acc[6]  += w0 * c0; acc[7]  += w0 * c1; acc[8]  += w0 * c2;
            acc[9]  += w1 * c0; acc[10] += w1 * c1; acc[11] += w1 * c2;
            acc[12] += w2 * c0; acc[13] += w2 * c1; acc[14] += w2 * c2;
            acc[15] += w0;      acc[16] += w1;      acc[17] += w2;
            acc[18] += wv * c0; acc[19] += wv * c1; acc[20] += wv * c2;
            acc[21] += wv;
        }
    }

    // warp reduce all 22
#pragma unroll
    for (int k = 0; k < NSUM; k++)
#pragma unroll
        for (int off = 16; off > 0; off >>= 1)
            acc[k] += __shfl_xor_sync(0xFFFFFFFFu, acc[k], off);

    __shared__ float sm[8][NSUM];
    __shared__ float sfin[NSUM];
    int wid = threadIdx.x >> 5, lane = threadIdx.x & 31;
    if (lane == 0)
#pragma unroll
        for (int k = 0; k < NSUM; k++) sm[wid][k] = acc[k];
    __syncthreads();
    if (threadIdx.x < NSUM) {
        float s = 0.f;
#pragma unroll
        for (int ww = 0; ww < 8; ww++) s += sm[ww][threadIdx.x];
        sfin[threadIdx.x] = s;
    }
    __syncthreads();

    // ---- phase 2a: pose (warp 6, lane 0) — overlaps everything below ----
    if (threadIdx.x == 192) {
        solve_pose(sfin, tsv, tout + b * 16);
    }

    // ---- phase 2b: publish norm partial + grid-wide ticket sync (warp 0,
    //      whole warp converged to keep bar.sync semantics safe) ----
    if (wid == 0) {
        unsigned int ticket = 0;
        if (lane == 0) {
            const float* s = sfin;
            float nq = 3.f * (s[0]*s[0] + s[3]*s[3] + s[5]*s[5])
                     + 6.f * (s[1]*s[1] + s[2]*s[2] + s[4]*s[4]);
#pragma unroll
            for (int k = 6; k < 15; k++) nq += 2.f * s[k] * s[k];
#pragma unroll
            for (int k = 15; k < 18; k++) nq += 6.f * s[k] * s[k];
#pragma unroll
            for (int k = 18; k < 21; k++) nq += 2.f * s[k] * s[k];
            nq += 3.f * s[21] * s[21];
            g_sq[b] = nq;
            __threadfence();
            ticket = atomicAdd(&g_ctr, 1u);
        }
        ticket = __shfl_sync(0xFFFFFFFFu, ticket, 0);
        unsigned int target = ((ticket >> 8) + 1u) << 8;   // next multiple of 256
        while (*((volatile unsigned int*)&g_ctr) < target) { }
        __threadfence();
    }

    // ---- phase 3+4: warps 0-5 (192 threads) ----
    if (threadIdx.x < 192) {
        asm volatile("bar.sync 1, 192;" ::: "memory");

        // per-warp deterministic inv_scale (identical in every warp/block)
        float v = 0.f;
#pragma unroll
        for (int i = 0; i < 8; i++)
            v += __ldcg(&g_sq[lane + 32 * i]);
#pragma unroll
        for (int off = 16; off > 0; off >>= 1)
            v += __shfl_xor_sync(0xFFFFFFFFu, v, off);
        float x = rsqrtf(v);
        x = x * (1.5f - 0.5f * v * x * x);  // Newton refine

        if (threadIdx.x < 169)
            qout[b * 169 + threadIdx.x] = q_entry(sfin, threadIdx.x) * x;
    }
}

// ---------------------------------------------------------------------------
extern "C" void kernel_launch(void* const* d_in, const int* in_sizes, int n_in,
                              void* d_out, int out_size)
{
    const float* src = (const float*)d_in[0];
    const float* trg = (const float*)d_in[1];
    const float* w   = (const float*)d_in[2];
    const float* tsv = (const float*)d_in[3];
    float* out  = (float*)d_out;
    float* tout = out;                 // (B,4,4) = 4096 floats
    float* qout = out + BB * 16;       // (B,13,13) = 43264 floats

    fused_all<<<BB, 256>>>(src, trg, w, tsv, tout, qout);
}